// round 5
// baseline (speedup 1.0000x reference)
#include <cuda_runtime.h>
#include <cuda_bf16.h>

// ---------------- problem constants ----------------
#define N0 6912      // 48*48*3
#define N1 27648     // 96*96*3
#define N2 110592    // 192*192*3
#define NTOT 145152
#define NBLK 148
#define NTHR 1024
#define MAXB 100
#define CCAP 4096
#define STARGET 1000u
#define TW 36288      // total warps in K1 (NTOT/4)
#define K1BLK 2268    // TW/16
#define DSBYTES 131072

// ---------------- scratch (device globals) ----------------
__device__ float    g_conf[NTOT];
__device__ unsigned g_keysA[NTOT];
__device__ unsigned g_hist16[65536];
__device__ unsigned g_candK[CCAP], g_candV[CCAP];
__device__ float4   g_candBox[CCAP];
__device__ int      g_candCls[CCAP];
__device__ float4   g_bboxFB[NTOT];   // fallback-only scratch
__device__ unsigned g_maxp, g_minp, g_ticket, g_overflow;
__device__ unsigned g_barcnt, g_barrel;

// order-preserving float<->uint encodings
__device__ __forceinline__ unsigned enc_ord(float f) {
    unsigned u = __float_as_uint(f);
    return (u & 0x80000000u) ? ~u : (u ^ 0x80000000u);
}
__device__ __forceinline__ float dec_ord(unsigned o) {
    unsigned u = (o & 0x80000000u) ? (o ^ 0x80000000u) : ~o;
    return __uint_as_float(u);
}

__device__ __forceinline__ bool iou_gt_half(float4 a, float areaA, float4 b, float areaB) {
    float iw = fminf(a.z, b.z) - fmaxf(a.x, b.x); iw = fmaxf(iw, 0.0f);
    float ih = fminf(a.w, b.w) - fmaxf(a.y, b.y); ih = fmaxf(ih, 0.0f);
    float inter = iw * ih;
    float iou = __fdiv_rn(inter, areaA + areaB - inter);
    return iou > 0.5f;
}

__device__ __forceinline__ const float* box_ptr(int gw,
        const float* g0, const float* g1, const float* g2,
        int& H, int& abase, int& local) {
    if (gw < N0)      { H = 48;  abase = 12; local = gw;           return g0 + (size_t)local * 85; }
    if (gw < N0 + N1) { H = 96;  abase = 6;  local = gw - N0;      return g1 + (size_t)local * 85; }
    H = 192; abase = 0; local = gw - N0 - N1; return g2 + (size_t)local * 85;
}

__device__ __forceinline__ float4 geom(const float* p, int local, int H, int abase,
                                       const float* anch) {
    float x = p[0], y = p[1], wv = p[2], hv = p[3];
    int a = local % 3;
    int cell = local / 3;
    int cx = cell % H;   // W == H
    int cy = cell / H;
    float aw = anch[abase + a * 2 + 0];
    float ah = anch[abase + a * 2 + 1];
    float bw = expf(wv) * aw;
    float bh = expf(hv) * ah;
    float Hf = (float)H;
    float X = __fdiv_rn(x + (float)cx, Hf);
    float Y = __fdiv_rn(y + (float)cy, Hf);
    return make_float4(X - bw * 0.5f, Y - bh * 0.5f, X + bw * 0.5f, Y + bh * 0.5f);
}

// ---------------- grid barrier ----------------
__device__ __forceinline__ void gridbar(unsigned k) {
    __syncthreads();
    if (threadIdx.x == 0) {
        __threadfence();
        unsigned v = atomicAdd(&g_barcnt, 1u);
        if (v + 1u == k * (unsigned)NBLK) {
            __threadfence();
            atomicExch(&g_barrel, k);
        } else {
            unsigned r;
            do {
                asm volatile("ld.acquire.gpu.u32 %0, [%1];" : "=r"(r) : "l"(&g_barrel) : "memory");
            } while (r < k);
        }
    }
    __syncthreads();
}

// ---------------- K0: reset ----------------
__global__ void reset_kernel() {
    g_barcnt = 0u;
    g_barrel = 0u;
    g_maxp = 0u;
    g_minp = 0xFFFFFFFFu;
    g_ticket = 0u;
    g_overflow = 0u;
}

// ---------------- K1: streaming conf + M/m reduction ----------------
__global__ void __launch_bounds__(512)
k1_kernel(const float* __restrict__ g0,
          const float* __restrict__ g1,
          const float* __restrict__ g2) {
    int tid = threadIdx.x;
    int lane = tid & 31;
    int wid = tid >> 5;

    unsigned gtid = blockIdx.x * 512u + (unsigned)tid;
    if (gtid < 65536u) g_hist16[gtid] = 0u;

    int w = blockIdx.x * 16 + wid;   // 0..TW-1
    float bv[4], cf[4];

    #pragma unroll
    for (int it = 0; it < 4; ++it) {
        int gw = w + it * TW;
        int H, abase, local;
        const float* p = box_ptr(gw, g0, g1, g2, H, abase, local);
        float v0 = p[5 + lane];
        float v1 = p[37 + lane];
        float v2 = (lane < 16) ? p[69 + lane] : -3.4e38f;
        bv[it] = fmaxf(fmaxf(v0, v1), v2);
        cf[it] = (lane == 0) ? p[4] : 0.0f;
    }
    #pragma unroll
    for (int it = 0; it < 4; ++it) {
        #pragma unroll
        for (int off = 16; off; off >>= 1)
            bv[it] = fmaxf(bv[it], __shfl_xor_sync(0xffffffffu, bv[it], off));
    }
    if (lane == 0) {
        #pragma unroll
        for (int it = 0; it < 4; ++it) g_conf[w + it * TW] = cf[it];
    }

    float M = fmaxf(fmaxf(bv[0], bv[1]), fmaxf(bv[2], bv[3]));
    float m = fminf(fminf(bv[0], bv[1]), fminf(bv[2], bv[3]));
    __shared__ float sM[16], sm[16];
    if (lane == 0) { sM[wid] = M; sm[wid] = m; }
    __syncthreads();
    if (tid == 0) {
        #pragma unroll
        for (int i = 1; i < 16; ++i) { M = fmaxf(M, sM[i]); m = fminf(m, sm[i]); }
        atomicMax(&g_maxp, enc_ord(M));
        atomicMin(&g_minp, enc_ord(m));
    }
}

// ---------------- K2: keys -> top-K -> candidate decode -> sort -> NMS ----------------
__global__ void __launch_bounds__(NTHR, 1)
k2_kernel(const float* __restrict__ g0,
          const float* __restrict__ g1,
          const float* __restrict__ g2,
          const float* __restrict__ anch,
          float* __restrict__ out, int out_size) {
    extern __shared__ unsigned char DS[];
    unsigned* ka = (unsigned*)DS;                       // 16384
    unsigned* va = (unsigned*)(DS + 16384);
    unsigned* kb = (unsigned*)(DS + 32768);
    unsigned* vb = (unsigned*)(DS + 49152);
    float4*  sBox = (float4*)(DS + 65536);              // 65536 bytes
    unsigned (*wc)[256] = (unsigned (*)[256])(DS + 65536);  // alias (sort only)
    unsigned* s_scan = (unsigned*)DS;                   // alias of ka (cutoff only)

    __shared__ unsigned s_hb[256], s_rb[256];
    __shared__ int s_cstar;
    __shared__ int s_opos[MAXB];
    __shared__ int s_fbidx[MAXB];
    __shared__ float4 selB[MAXB];
    __shared__ float  selA[MAXB];
    __shared__ float4 o_box[MAXB];
    __shared__ float  o_score[MAXB];
    __shared__ int    o_cls[MAXB];
    __shared__ unsigned s_alive[32];
    __shared__ int s_nsel, s_nties, s_first;

    const int tid  = threadIdx.x;
    const int b    = blockIdx.x;
    const int lane = tid & 31;
    const int wid  = tid >> 5;
    unsigned bk = 0;

    // ================= P1: keys + 16-bit histogram =================
    {
        float M = dec_ord(g_maxp);
        float m = dec_ord(g_minp);
        for (int i = b * NTHR + tid; i < NTOT; i += NBLK * NTHR) {
            float c = g_conf[i];
            float score = fmaxf(c * M, c * m);
            unsigned key = (score > 0.0f) ? ~enc_ord(score) : 0xFFFFFFFFu;
            g_keysA[i] = key;
            atomicAdd(&g_hist16[key >> 16], 1u);
        }
    }
    gridbar(++bk);

    // ================= P2: cutoff (redundant per block) + compaction =================
    unsigned totalvalid;
    int cstar;
    {
        unsigned part = 0;
        int base = tid * 64;
        #pragma unroll 8
        for (int i = 0; i < 64; ++i) part += g_hist16[base + i];
        s_scan[tid] = part;
        __syncthreads();
        unsigned x = part;
        for (int off = 1; off < 1024; off <<= 1) {
            unsigned add = (tid >= off) ? s_scan[tid - off] : 0u;
            __syncthreads();
            x += add;
            s_scan[tid] = x;
            __syncthreads();
        }
        totalvalid = s_scan[511];   // bins 0x0000..0x7FFF = valid (score>0)
        unsigned S = STARGET < totalvalid ? STARGET : totalvalid;
        if (tid == 0) s_cstar = -1;
        __syncthreads();
        if (S > 0 && tid < 512) {
            unsigned prev = (tid == 0) ? 0u : s_scan[tid - 1];
            if (x >= S && prev < S) {
                unsigned run = prev;
                for (int i = 0; i < 64; ++i) {
                    run += g_hist16[base + i];
                    if (run >= S) { s_cstar = base + i; break; }
                }
            }
        }
        __syncthreads();
        cstar = s_cstar;
    }
    if (cstar >= 0) {
        for (int i = b * NTHR + tid; i < NTOT; i += NBLK * NTHR) {
            unsigned key = g_keysA[i];
            if ((int)(key >> 16) <= cstar) {
                unsigned pos = atomicAdd(&g_ticket, 1u);
                if (pos < CCAP) { g_candK[pos] = key; g_candV[pos] = (unsigned)i; }
                else            { g_overflow = 1u; }
            }
        }
    }
    gridbar(++bk);

    // ================= P3: candidate decode (all blocks, warp per candidate) =================
    int C = (int)(g_ticket < (unsigned)CCAP ? g_ticket : (unsigned)CCAP);
    for (int idx = b * 32 + wid; idx < C; idx += NBLK * 32) {
        int gw = (int)g_candV[idx];
        int H, abase, local;
        const float* p = box_ptr(gw, g0, g1, g2, H, abase, local);

        float bvv = -3.4e38f;
        int bi = 0;
        for (int c = lane; c < 80; c += 32) {
            float v = p[5 + c];
            if (v > bvv) { bvv = v; bi = c; }
        }
        #pragma unroll
        for (int off = 16; off; off >>= 1) {
            float ov = __shfl_xor_sync(0xffffffffu, bvv, off);
            int   oi = __shfl_xor_sync(0xffffffffu, bi, off);
            if (ov > bvv || (ov == bvv && oi < bi)) { bvv = ov; bi = oi; }
        }
        if (lane == 0) {
            g_candBox[idx] = geom(p, local, H, abase, anch);
            g_candCls[idx] = bi;
        }
    }
    gridbar(++bk);

    if (b != 0) return;

    // ================= block 0: sort + NMS + output =================
    int ovf = (int)g_overflow;
    if (tid == 0) { s_nsel = 0; s_nties = 0; }
    __syncthreads();

    if (C > 0) {
        int nwv = (C + 1023) >> 10;
        int NP = nwv << 10;
        for (int i = tid; i < NP; i += NTHR) {
            if (i < C) { ka[i] = g_candK[i]; va[i] = (unsigned)i; }
            else       { ka[i] = 0xFFFFFFFFu; va[i] = 0u; }
        }
        __syncthreads();

        // ---- 4x8-bit stable LSD radix sort in smem ----
        for (int pass = 0; pass < 4; ++pass) {
            unsigned* sk = (pass & 1) ? kb : ka;
            unsigned* sv = (pass & 1) ? vb : va;
            unsigned* dk = (pass & 1) ? ka : kb;
            unsigned* dv = (pass & 1) ? va : vb;
            int sh = pass * 8;

            if (tid < 256) s_hb[tid] = 0u;
            __syncthreads();
            for (int i = tid; i < NP; i += NTHR)
                atomicAdd(&s_hb[(sk[i] >> sh) & 255u], 1u);
            __syncthreads();

            unsigned x = (tid < 256) ? s_hb[tid] : 0u;
            unsigned cnt = x;
            for (int off = 1; off < 256; off <<= 1) {
                unsigned add = (tid < 256 && tid >= off) ? s_hb[tid - off] : 0u;
                __syncthreads();
                if (tid < 256) { x += add; s_hb[tid] = x; }
                __syncthreads();
            }
            if (tid < 256) s_rb[tid] = x - cnt;   // exclusive base
            __syncthreads();

            for (int w = 0; w < nwv; ++w) {
                for (int j = tid; j < 32 * 256; j += NTHR) ((unsigned*)wc)[j] = 0u;
                __syncthreads();
                int e = (w << 10) + tid;
                unsigned key = sk[e];
                unsigned d = (key >> sh) & 255u;
                unsigned mask = __match_any_sync(0xffffffffu, d);
                unsigned lr = __popc(mask & ((1u << lane) - 1u));
                if (lr == 0) wc[wid][d] = __popc(mask);
                __syncthreads();
                if (tid < 256) {
                    unsigned run = s_rb[tid];
                    #pragma unroll
                    for (int ww = 0; ww < 32; ++ww) {
                        unsigned c2 = wc[ww][tid];
                        wc[ww][tid] = run;
                        run += c2;
                    }
                    s_rb[tid] = run;
                }
                __syncthreads();
                unsigned dst = wc[wid][d] + lr;
                dk[dst] = key;
                dv[dst] = sv[e];
                __syncthreads();
            }
        }
        // result in ka/va (slots)

        // ---- exact tie-break: equal keys -> ascending original box idx ----
        for (int i = tid; i < C; i += NTHR)
            if (i > 0 && ka[i] == ka[i - 1]) atomicAdd(&s_nties, 1);
        __syncthreads();
        if (s_nties) {
            for (int i = tid; i < C; i += NTHR) {
                if ((i == 0 || ka[i] != ka[i - 1]) && i + 1 < C && ka[i + 1] == ka[i]) {
                    int j = i + 1;
                    while (j < C && ka[j] == ka[i]) j++;
                    for (int a = i + 1; a < j; ++a) {
                        unsigned slot = va[a];
                        unsigned key2 = g_candV[slot];
                        int p2 = a - 1;
                        while (p2 >= i && g_candV[va[p2]] > key2) { va[p2 + 1] = va[p2]; --p2; }
                        va[p2 + 1] = slot;
                    }
                }
            }
        }
        __syncthreads();

        // ---- gather candidate boxes in sorted order ----
        for (int i = tid; i < C; i += NTHR) sBox[i] = g_candBox[va[i]];
        __syncthreads();

        // ---- block-parallel chunked greedy NMS ----
        {
            int nsel = 0;
            for (int base = 0; base < C && nsel < MAXB; base += NTHR) {
                int i = base + tid;
                float4 bx = make_float4(0.f, 0.f, 0.f, 0.f);
                float ar = 0.f;
                bool alive = (i < C);
                if (alive) {
                    bx = sBox[i];
                    ar = (bx.z - bx.x) * (bx.w - bx.y);
                    // prefilter vs already-selected boxes (from prior chunks)
                    for (int s = 0; s < nsel; ++s) {
                        if (iou_gt_half(bx, ar, selB[s], selA[s])) { alive = false; break; }
                    }
                }
                unsigned bal = __ballot_sync(0xffffffffu, alive);
                if (lane == 0) s_alive[wid] = bal;
                __syncthreads();

                int hint = 0;
                while (nsel < MAXB) {
                    if (tid == 0) {
                        int f = -1;
                        for (int w2 = hint; w2 < 32; ++w2) {
                            unsigned m2 = s_alive[w2];
                            if (m2) { f = (w2 << 5) + __ffs(m2) - 1; break; }
                        }
                        s_first = f;
                        if (f >= 0) s_opos[nsel] = base + f;
                    }
                    __syncthreads();
                    int f = s_first;
                    if (f < 0) break;
                    hint = f >> 5;
                    float4 sb = sBox[base + f];
                    float sa = (sb.z - sb.x) * (sb.w - sb.y);
                    if (tid == f) { selB[nsel] = bx; selA[nsel] = ar; }
                    nsel++;
                    if (alive && (tid == f || iou_gt_half(bx, ar, sb, sa))) alive = false;
                    unsigned bal2 = __ballot_sync(0xffffffffu, alive);
                    if (lane == 0) s_alive[wid] = bal2;
                    __syncthreads();
                }
            }
            if (tid == 0) s_nsel = nsel;
        }
        __syncthreads();

        // ---- fill output arrays ----
        int ns = s_nsel;
        for (int j = tid; j < ns; j += NTHR) {
            int i = s_opos[j];
            o_box[j]   = sBox[i];
            o_score[j] = dec_ord(~ka[i]);
            o_cls[j]   = g_candCls[va[i]];
        }
        __syncthreads();
    }

    // ================= fallback (exactness guard; normally never taken) =================
    {
        bool need_fb = (s_nsel < MAXB) && (ovf || totalvalid > (unsigned)C);
        if (need_fb) {
            // decode all bboxes (block0 alone)
            for (int gw = tid; gw < NTOT; gw += NTHR) {
                int H, abase, local;
                const float* p = box_ptr(gw, g0, g1, g2, H, abase, local);
                g_bboxFB[gw] = geom(p, local, H, abase, anch);
            }
            if (tid == 0) s_nsel = 0;
            __syncthreads();
            unsigned long long* red = (unsigned long long*)kb;
            for (int r = 0; r < MAXB; ++r) {
                unsigned long long best = ~0ull;
                for (int i = tid; i < NTOT; i += NTHR) {
                    unsigned k = g_keysA[i];
                    if (k < 0x80000000u) {
                        unsigned long long cmp = ((unsigned long long)k << 32) | (unsigned)i;
                        if (cmp < best) best = cmp;
                    }
                }
                red[tid] = best;
                __syncthreads();
                for (int off = 512; off; off >>= 1) {
                    if (tid < off && red[tid + off] < red[tid]) red[tid] = red[tid + off];
                    __syncthreads();
                }
                best = red[0];
                __syncthreads();
                if (best == ~0ull) break;
                unsigned j = (unsigned)(best & 0xFFFFFFFFu);
                float4 bj = g_bboxFB[j];
                float aj = (bj.z - bj.x) * (bj.w - bj.y);
                if (tid == 0) {
                    int n = s_nsel;
                    o_box[n]   = bj;
                    o_score[n] = dec_ord(~(unsigned)(best >> 32));
                    s_fbidx[n] = (int)j;
                    s_nsel = n + 1;
                }
                for (int i = tid; i < NTOT; i += NTHR) {
                    unsigned k = g_keysA[i];
                    if (k < 0x80000000u) {
                        float4 bi = g_bboxFB[i];
                        float ai = (bi.z - bi.x) * (bi.w - bi.y);
                        if (iou_gt_half(bi, ai, bj, aj)) g_keysA[i] = 0xFFFFFFFFu;
                    }
                }
                __syncthreads();
            }
            // classes for fallback selections (serial argmax per selection)
            for (int j2 = tid; j2 < s_nsel; j2 += NTHR) {
                int gw = s_fbidx[j2];
                int H, abase, local;
                const float* p = box_ptr(gw, g0, g1, g2, H, abase, local);
                float bestv = -3.4e38f; int bi = 0;
                for (int c = 0; c < 80; ++c) {
                    float v = p[5 + c];
                    if (v > bestv) { bestv = v; bi = c; }
                }
                o_cls[j2] = bi;
            }
            __syncthreads();
        }
    }

    // ================= output =================
    int ns = s_nsel;
    for (int i = tid; i < out_size; i += NTHR) {
        float v = 0.0f;
        if (i < 400) {
            int j = i >> 2;
            if (j < ns) v = ((float*)o_box)[i];
        } else if (i < 500) {
            int j = i - 400;
            if (j < ns) v = o_score[j];
        } else if (i < 600) {
            int j = i - 500;
            if (j < ns) v = (float)o_cls[j];
        } else if (i == 600) {
            v = (float)ns;
        }
        out[i] = v;
    }
}

// ---------------- launch ----------------
extern "C" void kernel_launch(void* const* d_in, const int* in_sizes, int n_in,
                              void* d_out, int out_size) {
    const float* g0   = (const float*)d_in[0];
    const float* g1   = (const float*)d_in[1];
    const float* g2   = (const float*)d_in[2];
    const float* anch = (const float*)d_in[3];
    float* out = (float*)d_out;

    cudaFuncSetAttribute(k2_kernel, cudaFuncAttributeMaxDynamicSharedMemorySize, DSBYTES);
    reset_kernel<<<1, 1>>>();
    k1_kernel<<<K1BLK, 512>>>(g0, g1, g2);
    k2_kernel<<<NBLK, NTHR, DSBYTES>>>(g0, g1, g2, anch, out, out_size);
}

// round 7
// speedup vs baseline: 1.0020x; 1.0020x over previous
#include <cuda_runtime.h>
#include <cuda_bf16.h>

// ---------------- problem constants ----------------
#define N0 6912      // 48*48*3
#define N1 27648     // 96*96*3
#define N2 110592    // 192*192*3
#define NTOT 145152
#define NBLK 148
#define NTHR 1024
#define MAXB 100
#define CCAP 4096
#define STARGET 1000u
#define DSBYTES 131072
// K1 geometry
#define NB1 567      // NTOT/256
#define BPB 256      // boxes per K1 block
#define K1T 512
#define K1SM (BPB * 85 * 4)   // 87040 bytes

// ---------------- scratch (device globals) ----------------
__device__ float    g_conf[NTOT];
__device__ unsigned g_keysA[NTOT];
__device__ unsigned g_hist16[65536];
__device__ unsigned g_candK[CCAP], g_candV[CCAP];
__device__ float4   g_candBox[CCAP];
__device__ int      g_candCls[CCAP];
__device__ float4   g_bboxFB[NTOT];   // fallback-only scratch
__device__ float    g_partM[NB1], g_partm[NB1];
__device__ unsigned g_ticket, g_overflow;
__device__ unsigned g_barcnt, g_barrel, g_done;

// order-preserving float<->uint encodings
__device__ __forceinline__ unsigned enc_ord(float f) {
    unsigned u = __float_as_uint(f);
    return (u & 0x80000000u) ? ~u : (u ^ 0x80000000u);
}
__device__ __forceinline__ float dec_ord(unsigned o) {
    unsigned u = (o & 0x80000000u) ? (o ^ 0x80000000u) : ~o;
    return __uint_as_float(u);
}

__device__ __forceinline__ bool iou_gt_half(float4 a, float areaA, float4 b, float areaB) {
    float iw = fminf(a.z, b.z) - fmaxf(a.x, b.x); iw = fmaxf(iw, 0.0f);
    float ih = fminf(a.w, b.w) - fmaxf(a.y, b.y); ih = fmaxf(ih, 0.0f);
    float inter = iw * ih;
    float iou = __fdiv_rn(inter, areaA + areaB - inter);
    return iou > 0.5f;
}

__device__ __forceinline__ const float* box_ptr(int gw,
        const float* g0, const float* g1, const float* g2,
        int& H, int& abase, int& local) {
    if (gw < N0)      { H = 48;  abase = 12; local = gw;           return g0 + (size_t)local * 85; }
    if (gw < N0 + N1) { H = 96;  abase = 6;  local = gw - N0;      return g1 + (size_t)local * 85; }
    H = 192; abase = 0; local = gw - N0 - N1; return g2 + (size_t)local * 85;
}

__device__ __forceinline__ float4 geom(const float* p, int local, int H, int abase,
                                       const float* anch) {
    float x = p[0], y = p[1], wv = p[2], hv = p[3];
    int a = local % 3;
    int cell = local / 3;
    int cx = cell % H;   // W == H
    int cy = cell / H;
    float aw = anch[abase + a * 2 + 0];
    float ah = anch[abase + a * 2 + 1];
    float bw = expf(wv) * aw;
    float bh = expf(hv) * ah;
    float Hf = (float)H;
    float X = __fdiv_rn(x + (float)cx, Hf);
    float Y = __fdiv_rn(y + (float)cy, Hf);
    return make_float4(X - bw * 0.5f, Y - bh * 0.5f, X + bw * 0.5f, Y + bh * 0.5f);
}

// ---------------- grid barrier ----------------
__device__ __forceinline__ void gridbar(unsigned k) {
    __syncthreads();
    if (threadIdx.x == 0) {
        __threadfence();
        unsigned v = atomicAdd(&g_barcnt, 1u);
        if (v + 1u == k * (unsigned)NBLK) {
            __threadfence();
            atomicExch(&g_barrel, k);
        } else {
            unsigned r;
            do {
                asm volatile("ld.acquire.gpu.u32 %0, [%1];" : "=r"(r) : "l"(&g_barrel) : "memory");
            } while (r < k);
        }
    }
    __syncthreads();
}

// ---------------- K1: smem-staged streaming conf + per-block M/m ----------------
__global__ void __launch_bounds__(K1T)
k1_kernel(const float* __restrict__ g0,
          const float* __restrict__ g1,
          const float* __restrict__ g2) {
    extern __shared__ float S[];
    const int b = blockIdx.x;
    const int tid = threadIdx.x;
    const int lane = tid & 31;
    const int wid = tid >> 5;

    unsigned gi = b * (unsigned)K1T + tid;
    if (gi < 65536u) g_hist16[gi] = 0u;

    const float* src; int boxbase; int gbase;
    if (b < 27)       { src = g0; boxbase = b * BPB;         gbase = 0; }
    else if (b < 135) { src = g1; boxbase = (b - 27) * BPB;  gbase = N0; }
    else              { src = g2; boxbase = (b - 135) * BPB; gbase = N0 + N1; }

    // bulk coalesced copy: 256 boxes * 85 floats = 5440 float4
    const float4* in = (const float4*)(src + (size_t)boxbase * 85);
    float4* S4 = (float4*)S;
    const int NF4 = BPB * 85 / 4;   // 5440
    #pragma unroll 4
    for (int i = tid; i < NF4; i += K1T) S4[i] = in[i];
    __syncthreads();

    // 2 threads per box: halves of the 80 class probs
    int box = tid >> 1, half = tid & 1;
    const float* pb = S + box * 85;
    float mx = -3.4e38f;
    int base = 5 + half * 40;
    #pragma unroll 8
    for (int i = 0; i < 40; ++i) mx = fmaxf(mx, pb[base + i]);
    mx = fmaxf(mx, __shfl_xor_sync(0xffffffffu, mx, 1));   // both halves now have box max
    if (half == 0) g_conf[gbase + boxbase + box] = pb[4];

    // block reduce M/m (duplicates don't affect max/min)
    float M = mx, m = mx;
    #pragma unroll
    for (int off = 16; off > 1; off >>= 1) {
        M = fmaxf(M, __shfl_xor_sync(0xffffffffu, M, off));
        m = fminf(m, __shfl_xor_sync(0xffffffffu, m, off));
    }
    __shared__ float aM[16], am[16];
    if (lane == 0) { aM[wid] = M; am[wid] = m; }
    __syncthreads();
    if (tid == 0) {
        #pragma unroll
        for (int i = 1; i < 16; ++i) { M = fmaxf(M, aM[i]); m = fminf(m, am[i]); }
        g_partM[b] = M;
        g_partm[b] = m;
    }
}

// ---------------- K2: keys -> top-K -> candidate decode -> sort -> NMS ----------------
__global__ void __launch_bounds__(NTHR, 1)
k2_kernel(const float* __restrict__ g0,
          const float* __restrict__ g1,
          const float* __restrict__ g2,
          const float* __restrict__ anch,
          float* __restrict__ out, int out_size) {
    extern __shared__ unsigned char DS[];
    unsigned* ka = (unsigned*)DS;                       // 16384
    unsigned* va = (unsigned*)(DS + 16384);
    unsigned* kb = (unsigned*)(DS + 32768);
    unsigned* vb = (unsigned*)(DS + 49152);
    float4*  sBox = (float4*)(DS + 65536);              // 65536 bytes
    unsigned (*wc)[256] = (unsigned (*)[256])(DS + 65536);  // alias (sort only)
    unsigned* s_scan = (unsigned*)DS;                   // alias of ka (cutoff only)

    __shared__ unsigned s_hb[256], s_rb[256];
    __shared__ float s_rM[32], s_rm[32];
    __shared__ float s_MM, s_mm;
    __shared__ int s_cstar;
    __shared__ int s_opos[MAXB];
    __shared__ int s_fbidx[MAXB];
    __shared__ float4 selB[MAXB];
    __shared__ float  selA[MAXB];
    __shared__ float4 o_box[MAXB];
    __shared__ float  o_score[MAXB];
    __shared__ int    o_cls[MAXB];
    __shared__ unsigned s_alive[32];
    __shared__ int s_nsel, s_nties, s_first;

    const int tid  = threadIdx.x;
    const int b    = blockIdx.x;
    const int lane = tid & 31;
    const int wid  = tid >> 5;
    unsigned bk = 0;

    // ================= P1: M/m from partials, then keys + 16-bit histogram =================
    if (b == 0 && tid == 0) { g_ticket = 0u; g_overflow = 0u; }
    {
        float M = -3.4e38f, m = 3.4e38f;
        if (tid < NB1) { M = g_partM[tid]; m = g_partm[tid]; }
        #pragma unroll
        for (int off = 16; off; off >>= 1) {
            M = fmaxf(M, __shfl_xor_sync(0xffffffffu, M, off));
            m = fminf(m, __shfl_xor_sync(0xffffffffu, m, off));
        }
        if (lane == 0) { s_rM[wid] = M; s_rm[wid] = m; }
        __syncthreads();
        if (tid == 0) {
            #pragma unroll
            for (int i = 1; i < 32; ++i) { M = fmaxf(M, s_rM[i]); m = fminf(m, s_rm[i]); }
            s_MM = M; s_mm = m;
        }
        __syncthreads();
        M = s_MM; m = s_mm;
        for (int i = b * NTHR + tid; i < NTOT; i += NBLK * NTHR) {
            float c = g_conf[i];
            float score = fmaxf(c * M, c * m);
            unsigned key = (score > 0.0f) ? ~enc_ord(score) : 0xFFFFFFFFu;
            g_keysA[i] = key;
            atomicAdd(&g_hist16[key >> 16], 1u);
        }
    }
    gridbar(++bk);

    // ================= P2: cutoff (redundant per block) + compaction =================
    unsigned totalvalid;
    int cstar;
    {
        unsigned part = 0;
        int base = tid * 64;
        #pragma unroll 8
        for (int i = 0; i < 64; ++i) part += g_hist16[base + i];
        s_scan[tid] = part;
        __syncthreads();
        unsigned x = part;
        for (int off = 1; off < 1024; off <<= 1) {
            unsigned add = (tid >= off) ? s_scan[tid - off] : 0u;
            __syncthreads();
            x += add;
            s_scan[tid] = x;
            __syncthreads();
        }
        totalvalid = s_scan[511];   // bins 0x0000..0x7FFF = valid (score>0)
        unsigned S = STARGET < totalvalid ? STARGET : totalvalid;
        if (tid == 0) s_cstar = -1;
        __syncthreads();
        if (S > 0 && tid < 512) {
            unsigned prev = (tid == 0) ? 0u : s_scan[tid - 1];
            if (x >= S && prev < S) {
                unsigned run = prev;
                for (int i = 0; i < 64; ++i) {
                    run += g_hist16[base + i];
                    if (run >= S) { s_cstar = base + i; break; }
                }
            }
        }
        __syncthreads();
        cstar = s_cstar;
    }
    if (cstar >= 0) {
        for (int i = b * NTHR + tid; i < NTOT; i += NBLK * NTHR) {
            unsigned key = g_keysA[i];
            if ((int)(key >> 16) <= cstar) {
                unsigned pos = atomicAdd(&g_ticket, 1u);
                if (pos < CCAP) { g_candK[pos] = key; g_candV[pos] = (unsigned)i; }
                else            { g_overflow = 1u; }
            }
        }
    }
    gridbar(++bk);

    // ================= P3: candidate decode (all blocks, warp per candidate) =================
    int C = (int)(g_ticket < (unsigned)CCAP ? g_ticket : (unsigned)CCAP);
    for (int idx = b * 32 + wid; idx < C; idx += NBLK * 32) {
        int gw = (int)g_candV[idx];
        int H, abase, local;
        const float* p = box_ptr(gw, g0, g1, g2, H, abase, local);

        float bvv = -3.4e38f;
        int bi = 0;
        for (int c = lane; c < 80; c += 32) {
            float v = p[5 + c];
            if (v > bvv) { bvv = v; bi = c; }
        }
        #pragma unroll
        for (int off = 16; off; off >>= 1) {
            float ov = __shfl_xor_sync(0xffffffffu, bvv, off);
            int   oi = __shfl_xor_sync(0xffffffffu, bi, off);
            if (ov > bvv || (ov == bvv && oi < bi)) { bvv = ov; bi = oi; }
        }
        if (lane == 0) {
            g_candBox[idx] = geom(p, local, H, abase, anch);
            g_candCls[idx] = bi;
        }
    }

    // ---- done-counter: non-zero blocks publish P3 writes and exit ----
    if (b != 0) {
        __threadfence();
        __syncthreads();
        if (tid == 0) atomicAdd(&g_done, 1u);
        return;
    }
    // block 0 waits for everyone
    __threadfence();
    __syncthreads();
    if (tid == 0) {
        unsigned r;
        do {
            asm volatile("ld.acquire.gpu.u32 %0, [%1];" : "=r"(r) : "l"(&g_done) : "memory");
        } while (r < (unsigned)(NBLK - 1));
    }
    __syncthreads();

    // ================= block 0: sort + NMS + output =================
    int ovf = (int)g_overflow;
    if (tid == 0) { s_nsel = 0; s_nties = 0; }
    __syncthreads();

    if (C > 0) {
        int nwv = (C + 1023) >> 10;
        int NP = nwv << 10;
        for (int i = tid; i < NP; i += NTHR) {
            if (i < C) { ka[i] = g_candK[i]; va[i] = (unsigned)i; }
            else       { ka[i] = 0xFFFFFFFFu; va[i] = 0u; }
        }
        __syncthreads();

        // ---- 4x8-bit stable LSD radix sort in smem ----
        for (int pass = 0; pass < 4; ++pass) {
            unsigned* sk = (pass & 1) ? kb : ka;
            unsigned* sv = (pass & 1) ? vb : va;
            unsigned* dk = (pass & 1) ? ka : kb;
            unsigned* dv = (pass & 1) ? va : vb;
            int sh = pass * 8;

            if (tid < 256) s_hb[tid] = 0u;
            __syncthreads();
            for (int i = tid; i < NP; i += NTHR)
                atomicAdd(&s_hb[(sk[i] >> sh) & 255u], 1u);
            __syncthreads();

            unsigned x = (tid < 256) ? s_hb[tid] : 0u;
            unsigned cnt = x;
            for (int off = 1; off < 256; off <<= 1) {
                unsigned add = (tid < 256 && tid >= off) ? s_hb[tid - off] : 0u;
                __syncthreads();
                if (tid < 256) { x += add; s_hb[tid] = x; }
                __syncthreads();
            }
            if (tid < 256) s_rb[tid] = x - cnt;   // exclusive base
            __syncthreads();

            for (int w = 0; w < nwv; ++w) {
                for (int j = tid; j < 32 * 256; j += NTHR) ((unsigned*)wc)[j] = 0u;
                __syncthreads();
                int e = (w << 10) + tid;
                unsigned key = sk[e];
                unsigned d = (key >> sh) & 255u;
                unsigned mask = __match_any_sync(0xffffffffu, d);
                unsigned lr = __popc(mask & ((1u << lane) - 1u));
                if (lr == 0) wc[wid][d] = __popc(mask);
                __syncthreads();
                if (tid < 256) {
                    unsigned run = s_rb[tid];
                    #pragma unroll
                    for (int ww = 0; ww < 32; ++ww) {
                        unsigned c2 = wc[ww][tid];
                        wc[ww][tid] = run;
                        run += c2;
                    }
                    s_rb[tid] = run;
                }
                __syncthreads();
                unsigned dst = wc[wid][d] + lr;
                dk[dst] = key;
                dv[dst] = sv[e];
                __syncthreads();
            }
        }
        // result in ka/va (slots)

        // ---- exact tie-break: equal keys -> ascending original box idx ----
        for (int i = tid; i < C; i += NTHR)
            if (i > 0 && ka[i] == ka[i - 1]) atomicAdd(&s_nties, 1);
        __syncthreads();
        if (s_nties) {
            for (int i = tid; i < C; i += NTHR) {
                if ((i == 0 || ka[i] != ka[i - 1]) && i + 1 < C && ka[i + 1] == ka[i]) {
                    int j = i + 1;
                    while (j < C && ka[j] == ka[i]) j++;
                    for (int a = i + 1; a < j; ++a) {
                        unsigned slot = va[a];
                        unsigned key2 = g_candV[slot];
                        int p2 = a - 1;
                        while (p2 >= i && g_candV[va[p2]] > key2) { va[p2 + 1] = va[p2]; --p2; }
                        va[p2 + 1] = slot;
                    }
                }
            }
        }
        __syncthreads();

        // ---- gather candidate boxes in sorted order ----
        for (int i = tid; i < C; i += NTHR) sBox[i] = g_candBox[va[i]];
        __syncthreads();

        // ---- block-parallel chunked greedy NMS ----
        {
            int nsel = 0;
            for (int base = 0; base < C && nsel < MAXB; base += NTHR) {
                int i = base + tid;
                float4 bx = make_float4(0.f, 0.f, 0.f, 0.f);
                float ar = 0.f;
                bool alive = (i < C);
                if (alive) {
                    bx = sBox[i];
                    ar = (bx.z - bx.x) * (bx.w - bx.y);
                    for (int s = 0; s < nsel; ++s) {
                        if (iou_gt_half(bx, ar, selB[s], selA[s])) { alive = false; break; }
                    }
                }
                unsigned bal = __ballot_sync(0xffffffffu, alive);
                if (lane == 0) s_alive[wid] = bal;
                __syncthreads();

                int hint = 0;
                while (nsel < MAXB) {
                    if (tid == 0) {
                        int f = -1;
                        for (int w2 = hint; w2 < 32; ++w2) {
                            unsigned m2 = s_alive[w2];
                            if (m2) { f = (w2 << 5) + __ffs(m2) - 1; break; }
                        }
                        s_first = f;
                        if (f >= 0) s_opos[nsel] = base + f;
                    }
                    __syncthreads();
                    int f = s_first;
                    if (f < 0) break;
                    hint = f >> 5;
                    float4 sb = sBox[base + f];
                    float sa = (sb.z - sb.x) * (sb.w - sb.y);
                    if (tid == f) { selB[nsel] = bx; selA[nsel] = ar; }
                    nsel++;
                    if (alive && (tid == f || iou_gt_half(bx, ar, sb, sa))) alive = false;
                    unsigned bal2 = __ballot_sync(0xffffffffu, alive);
                    if (lane == 0) s_alive[wid] = bal2;
                    __syncthreads();
                }
            }
            if (tid == 0) s_nsel = nsel;
        }
        __syncthreads();

        // ---- fill output arrays ----
        int ns = s_nsel;
        for (int j = tid; j < ns; j += NTHR) {
            int i = s_opos[j];
            o_box[j]   = sBox[i];
            o_score[j] = dec_ord(~ka[i]);
            o_cls[j]   = g_candCls[va[i]];
        }
        __syncthreads();
    }

    // ================= fallback (exactness guard; normally never taken) =================
    {
        bool need_fb = (s_nsel < MAXB) && (ovf || totalvalid > (unsigned)C);
        if (need_fb) {
            for (int gw = tid; gw < NTOT; gw += NTHR) {
                int H, abase, local;
                const float* p = box_ptr(gw, g0, g1, g2, H, abase, local);
                g_bboxFB[gw] = geom(p, local, H, abase, anch);
            }
            if (tid == 0) s_nsel = 0;
            __syncthreads();
            unsigned long long* red = (unsigned long long*)kb;
            for (int r = 0; r < MAXB; ++r) {
                unsigned long long best = ~0ull;
                for (int i = tid; i < NTOT; i += NTHR) {
                    unsigned k = g_keysA[i];
                    if (k < 0x80000000u) {
                        unsigned long long cmp = ((unsigned long long)k << 32) | (unsigned)i;
                        if (cmp < best) best = cmp;
                    }
                }
                red[tid] = best;
                __syncthreads();
                for (int off = 512; off; off >>= 1) {
                    if (tid < off && red[tid + off] < red[tid]) red[tid] = red[tid + off];
                    __syncthreads();
                }
                best = red[0];
                __syncthreads();
                if (best == ~0ull) break;
                unsigned j = (unsigned)(best & 0xFFFFFFFFu);
                float4 bj = g_bboxFB[j];
                float aj = (bj.z - bj.x) * (bj.w - bj.y);
                if (tid == 0) {
                    int n = s_nsel;
                    o_box[n]   = bj;
                    o_score[n] = dec_ord(~(unsigned)(best >> 32));
                    s_fbidx[n] = (int)j;
                    s_nsel = n + 1;
                }
                for (int i = tid; i < NTOT; i += NTHR) {
                    unsigned k = g_keysA[i];
                    if (k < 0x80000000u) {
                        float4 bi = g_bboxFB[i];
                        float ai = (bi.z - bi.x) * (bi.w - bi.y);
                        if (iou_gt_half(bi, ai, bj, aj)) g_keysA[i] = 0xFFFFFFFFu;
                    }
                }
                __syncthreads();
            }
            for (int j2 = tid; j2 < s_nsel; j2 += NTHR) {
                int gw = s_fbidx[j2];
                int H, abase, local;
                const float* p = box_ptr(gw, g0, g1, g2, H, abase, local);
                float bestv = -3.4e38f; int bi = 0;
                for (int c = 0; c < 80; ++c) {
                    float v = p[5 + c];
                    if (v > bestv) { bestv = v; bi = c; }
                }
                o_cls[j2] = bi;
            }
            __syncthreads();
        }
    }

    // ================= output =================
    int ns = s_nsel;
    for (int i = tid; i < out_size; i += NTHR) {
        float v = 0.0f;
        if (i < 400) {
            int j = i >> 2;
            if (j < ns) v = ((float*)o_box)[i];
        } else if (i < 500) {
            int j = i - 400;
            if (j < ns) v = o_score[j];
        } else if (i < 600) {
            int j = i - 500;
            if (j < ns) v = (float)o_cls[j];
        } else if (i == 600) {
            v = (float)ns;
        }
        out[i] = v;
    }

    // ---- self-clean persistent state for next launch (all blocks already exited) ----
    __syncthreads();
    if (tid == 0) {
        g_barcnt = 0u;
        g_barrel = 0u;
        g_done   = 0u;
    }
}

// ---------------- launch ----------------
extern "C" void kernel_launch(void* const* d_in, const int* in_sizes, int n_in,
                              void* d_out, int out_size) {
    const float* g0   = (const float*)d_in[0];
    const float* g1   = (const float*)d_in[1];
    const float* g2   = (const float*)d_in[2];
    const float* anch = (const float*)d_in[3];
    float* out = (float*)d_out;

    cudaFuncSetAttribute(k1_kernel, cudaFuncAttributeMaxDynamicSharedMemorySize, K1SM);
    cudaFuncSetAttribute(k2_kernel, cudaFuncAttributeMaxDynamicSharedMemorySize, DSBYTES);
    k1_kernel<<<NB1, K1T, K1SM>>>(g0, g1, g2);
    k2_kernel<<<NBLK, NTHR, DSBYTES>>>(g0, g1, g2, anch, out, out_size);
}

// round 8
// speedup vs baseline: 1.2270x; 1.2246x over previous
#include <cuda_runtime.h>
#include <cuda_bf16.h>

// ---------------- problem constants ----------------
#define N0 6912      // 48*48*3
#define N1 27648     // 96*96*3
#define N2 110592    // 192*192*3
#define NTOT 145152
#define NBLK 148
#define NTHR 1024
#define MAXB 100
#define CCAP 4096
#define STARGET 1000u
#define HBINS 8192   // 13-bit histogram
#define DSBYTES 131072
// K1 geometry
#define NB1 567      // NTOT/256
#define BPB 256      // boxes per K1 block
#define K1T 512
#define K1SM (BPB * 85 * 4)   // 87040 bytes

// ---------------- scratch (device globals) ----------------
__device__ float    g_conf[NTOT];
__device__ unsigned g_keysA[NTOT];
__device__ unsigned g_hist13[HBINS];
__device__ unsigned g_candK[CCAP], g_candV[CCAP];
__device__ float4   g_candBox[CCAP];
__device__ int      g_candCls[CCAP];
__device__ float4   g_bboxFB[NTOT];   // fallback-only scratch
__device__ float    g_partM[NB1], g_partm[NB1];
__device__ unsigned g_ticket, g_overflow;
__device__ unsigned g_barcnt, g_barrel, g_done;

// order-preserving float<->uint encodings
__device__ __forceinline__ unsigned enc_ord(float f) {
    unsigned u = __float_as_uint(f);
    return (u & 0x80000000u) ? ~u : (u ^ 0x80000000u);
}
__device__ __forceinline__ float dec_ord(unsigned o) {
    unsigned u = (o & 0x80000000u) ? (o ^ 0x80000000u) : ~o;
    return __uint_as_float(u);
}

__device__ __forceinline__ bool iou_gt_half(float4 a, float areaA, float4 b, float areaB) {
    float iw = fminf(a.z, b.z) - fmaxf(a.x, b.x); iw = fmaxf(iw, 0.0f);
    float ih = fminf(a.w, b.w) - fmaxf(a.y, b.y); ih = fmaxf(ih, 0.0f);
    float inter = iw * ih;
    float iou = __fdiv_rn(inter, areaA + areaB - inter);
    return iou > 0.5f;
}

__device__ __forceinline__ const float* box_ptr(int gw,
        const float* g0, const float* g1, const float* g2,
        int& H, int& abase, int& local) {
    if (gw < N0)      { H = 48;  abase = 12; local = gw;           return g0 + (size_t)local * 85; }
    if (gw < N0 + N1) { H = 96;  abase = 6;  local = gw - N0;      return g1 + (size_t)local * 85; }
    H = 192; abase = 0; local = gw - N0 - N1; return g2 + (size_t)local * 85;
}

__device__ __forceinline__ float4 geom(const float* p, int local, int H, int abase,
                                       const float* anch) {
    float x = p[0], y = p[1], wv = p[2], hv = p[3];
    int a = local % 3;
    int cell = local / 3;
    int cx = cell % H;   // W == H
    int cy = cell / H;
    float aw = anch[abase + a * 2 + 0];
    float ah = anch[abase + a * 2 + 1];
    float bw = expf(wv) * aw;
    float bh = expf(hv) * ah;
    float Hf = (float)H;
    float X = __fdiv_rn(x + (float)cx, Hf);
    float Y = __fdiv_rn(y + (float)cy, Hf);
    return make_float4(X - bw * 0.5f, Y - bh * 0.5f, X + bw * 0.5f, Y + bh * 0.5f);
}

// ---------------- grid barrier ----------------
__device__ __forceinline__ void gridbar(unsigned k) {
    __syncthreads();
    if (threadIdx.x == 0) {
        __threadfence();
        unsigned v = atomicAdd(&g_barcnt, 1u);
        if (v + 1u == k * (unsigned)NBLK) {
            __threadfence();
            atomicExch(&g_barrel, k);
        } else {
            unsigned r;
            do {
                asm volatile("ld.acquire.gpu.u32 %0, [%1];" : "=r"(r) : "l"(&g_barrel) : "memory");
            } while (r < k);
        }
    }
    __syncthreads();
}

// ---------------- K1: smem-staged streaming conf + per-block M/m ----------------
__global__ void __launch_bounds__(K1T)
k1_kernel(const float* __restrict__ g0,
          const float* __restrict__ g1,
          const float* __restrict__ g2) {
    extern __shared__ float S[];
    const int b = blockIdx.x;
    const int tid = threadIdx.x;
    const int lane = tid & 31;
    const int wid = tid >> 5;

    unsigned gi = b * (unsigned)K1T + tid;
    if (gi < (unsigned)HBINS) g_hist13[gi] = 0u;

    const float* src; int boxbase; int gbase;
    if (b < 27)       { src = g0; boxbase = b * BPB;         gbase = 0; }
    else if (b < 135) { src = g1; boxbase = (b - 27) * BPB;  gbase = N0; }
    else              { src = g2; boxbase = (b - 135) * BPB; gbase = N0 + N1; }

    // bulk coalesced copy: 256 boxes * 85 floats = 5440 float4
    const float4* in = (const float4*)(src + (size_t)boxbase * 85);
    float4* S4 = (float4*)S;
    const int NF4 = BPB * 85 / 4;   // 5440
    #pragma unroll 4
    for (int i = tid; i < NF4; i += K1T) S4[i] = in[i];
    __syncthreads();

    // 2 threads per box: halves of the 80 class probs
    int box = tid >> 1, half = tid & 1;
    const float* pb = S + box * 85;
    float mx = -3.4e38f;
    int base = 5 + half * 40;
    #pragma unroll 8
    for (int i = 0; i < 40; ++i) mx = fmaxf(mx, pb[base + i]);
    mx = fmaxf(mx, __shfl_xor_sync(0xffffffffu, mx, 1));   // both halves now have box max
    if (half == 0) g_conf[gbase + boxbase + box] = pb[4];

    // block reduce M/m (duplicates don't affect max/min)
    float M = mx, m = mx;
    #pragma unroll
    for (int off = 16; off > 1; off >>= 1) {
        M = fmaxf(M, __shfl_xor_sync(0xffffffffu, M, off));
        m = fminf(m, __shfl_xor_sync(0xffffffffu, m, off));
    }
    __shared__ float aM[16], am[16];
    if (lane == 0) { aM[wid] = M; am[wid] = m; }
    __syncthreads();
    if (tid == 0) {
        #pragma unroll
        for (int i = 1; i < 16; ++i) { M = fmaxf(M, aM[i]); m = fminf(m, am[i]); }
        g_partM[b] = M;
        g_partm[b] = m;
    }
}

// ---------------- K2: keys -> top-K -> candidate decode -> sort -> NMS ----------------
__global__ void __launch_bounds__(NTHR, 1)
k2_kernel(const float* __restrict__ g0,
          const float* __restrict__ g1,
          const float* __restrict__ g2,
          const float* __restrict__ anch,
          float* __restrict__ out, int out_size) {
    extern __shared__ unsigned char DS[];
    unsigned* ka = (unsigned*)DS;                       // 16384
    unsigned* va = (unsigned*)(DS + 16384);
    unsigned* kb = (unsigned*)(DS + 32768);
    unsigned* vb = (unsigned*)(DS + 49152);
    float4*  sBox = (float4*)(DS + 65536);              // 65536 bytes
    unsigned (*wc)[256] = (unsigned (*)[256])(DS + 65536);  // alias (sort only)
    unsigned* s_hist = (unsigned*)DS;                   // alias ka+va (cutoff only, 32KB)
    unsigned* s_part = (unsigned*)(DS + 32768);         // alias kb (cutoff only, 4KB)

    __shared__ unsigned s_hb[256], s_rb[256];
    __shared__ float s_rM[32], s_rm[32];
    __shared__ float s_MM, s_mm;
    __shared__ int s_cstar;
    __shared__ int s_opos[MAXB];
    __shared__ int s_fbidx[MAXB];
    __shared__ float4 selB[MAXB];
    __shared__ float  selA[MAXB];
    __shared__ float4 o_box[MAXB];
    __shared__ float  o_score[MAXB];
    __shared__ int    o_cls[MAXB];
    __shared__ unsigned s_alive[32];
    __shared__ int s_nsel, s_nties, s_first;

    const int tid  = threadIdx.x;
    const int b    = blockIdx.x;
    const int lane = tid & 31;
    const int wid  = tid >> 5;
    unsigned bk = 0;

    // ================= P1: M/m from partials, then keys + 13-bit histogram =================
    if (b == 0 && tid == 0) { g_ticket = 0u; g_overflow = 0u; }
    {
        float M = -3.4e38f, m = 3.4e38f;
        if (tid < NB1) { M = g_partM[tid]; m = g_partm[tid]; }
        #pragma unroll
        for (int off = 16; off; off >>= 1) {
            M = fmaxf(M, __shfl_xor_sync(0xffffffffu, M, off));
            m = fminf(m, __shfl_xor_sync(0xffffffffu, m, off));
        }
        if (lane == 0) { s_rM[wid] = M; s_rm[wid] = m; }
        __syncthreads();
        if (tid == 0) {
            #pragma unroll
            for (int i = 1; i < 32; ++i) { M = fmaxf(M, s_rM[i]); m = fminf(m, s_rm[i]); }
            s_MM = M; s_mm = m;
        }
        __syncthreads();
        M = s_MM; m = s_mm;
        for (int i = b * NTHR + tid; i < NTOT; i += NBLK * NTHR) {
            float c = g_conf[i];
            float score = fmaxf(c * M, c * m);
            unsigned key = (score > 0.0f) ? ~enc_ord(score) : 0xFFFFFFFFu;
            g_keysA[i] = key;
            atomicAdd(&g_hist13[key >> 19], 1u);
        }
    }
    gridbar(++bk);

    // ================= P2: cutoff via coalesced smem-staged scan + compaction =================
    unsigned totalvalid;
    int cstar;
    {
        // coalesced load of full 8192-bin histogram into smem
        #pragma unroll
        for (int i = 0; i < HBINS / NTHR; ++i)
            s_hist[tid + i * NTHR] = g_hist13[tid + i * NTHR];
        __syncthreads();
        // per-thread sum of its 8 contiguous bins
        unsigned part = 0;
        #pragma unroll
        for (int i = 0; i < 8; ++i) part += s_hist[tid * 8 + i];
        s_part[tid] = part;
        __syncthreads();
        unsigned x = part;
        for (int off = 1; off < 1024; off <<= 1) {
            unsigned add = (tid >= off) ? s_part[tid - off] : 0u;
            __syncthreads();
            x += add;
            s_part[tid] = x;
            __syncthreads();
        }
        totalvalid = s_part[511];   // bins 0..4095 = valid keys (score>0)
        unsigned S = STARGET < totalvalid ? STARGET : totalvalid;
        if (tid == 0) s_cstar = -1;
        __syncthreads();
        if (S > 0 && tid < 512) {
            unsigned prev = (tid == 0) ? 0u : s_part[tid - 1];
            if (x >= S && prev < S) {
                unsigned run = prev;
                #pragma unroll
                for (int i = 0; i < 8; ++i) {
                    run += s_hist[tid * 8 + i];
                    if (run >= S) { s_cstar = tid * 8 + i; break; }
                }
            }
        }
        __syncthreads();
        cstar = s_cstar;
    }
    if (cstar >= 0) {
        for (int i = b * NTHR + tid; i < NTOT; i += NBLK * NTHR) {
            unsigned key = g_keysA[i];
            if ((int)(key >> 19) <= cstar) {
                unsigned pos = atomicAdd(&g_ticket, 1u);
                if (pos < CCAP) { g_candK[pos] = key; g_candV[pos] = (unsigned)i; }
                else            { g_overflow = 1u; }
            }
        }
    }
    gridbar(++bk);

    // ================= P3: candidate decode (all blocks, warp per candidate) =================
    int C = (int)(g_ticket < (unsigned)CCAP ? g_ticket : (unsigned)CCAP);
    for (int idx = b * 32 + wid; idx < C; idx += NBLK * 32) {
        int gw = (int)g_candV[idx];
        int H, abase, local;
        const float* p = box_ptr(gw, g0, g1, g2, H, abase, local);

        float bvv = -3.4e38f;
        int bi = 0;
        for (int c = lane; c < 80; c += 32) {
            float v = p[5 + c];
            if (v > bvv) { bvv = v; bi = c; }
        }
        #pragma unroll
        for (int off = 16; off; off >>= 1) {
            float ov = __shfl_xor_sync(0xffffffffu, bvv, off);
            int   oi = __shfl_xor_sync(0xffffffffu, bi, off);
            if (ov > bvv || (ov == bvv && oi < bi)) { bvv = ov; bi = oi; }
        }
        if (lane == 0) {
            g_candBox[idx] = geom(p, local, H, abase, anch);
            g_candCls[idx] = bi;
        }
    }

    // ---- done-counter: non-zero blocks publish P3 writes and exit ----
    if (b != 0) {
        __threadfence();
        __syncthreads();
        if (tid == 0) atomicAdd(&g_done, 1u);
        return;
    }
    // block 0 waits for everyone
    __threadfence();
    __syncthreads();
    if (tid == 0) {
        unsigned r;
        do {
            asm volatile("ld.acquire.gpu.u32 %0, [%1];" : "=r"(r) : "l"(&g_done) : "memory");
        } while (r < (unsigned)(NBLK - 1));
    }
    __syncthreads();

    // ================= block 0: sort + NMS + output =================
    int ovf = (int)g_overflow;
    if (tid == 0) { s_nsel = 0; s_nties = 0; }
    __syncthreads();

    if (C > 0) {
        int nwv = (C + 1023) >> 10;
        int NP = nwv << 10;
        for (int i = tid; i < NP; i += NTHR) {
            if (i < C) { ka[i] = g_candK[i]; va[i] = (unsigned)i; }
            else       { ka[i] = 0xFFFFFFFFu; va[i] = 0u; }
        }
        __syncthreads();

        // ---- 4x8-bit stable LSD radix sort in smem ----
        for (int pass = 0; pass < 4; ++pass) {
            unsigned* sk = (pass & 1) ? kb : ka;
            unsigned* sv = (pass & 1) ? vb : va;
            unsigned* dk = (pass & 1) ? ka : kb;
            unsigned* dv = (pass & 1) ? va : vb;
            int sh = pass * 8;

            if (tid < 256) s_hb[tid] = 0u;
            __syncthreads();
            for (int i = tid; i < NP; i += NTHR)
                atomicAdd(&s_hb[(sk[i] >> sh) & 255u], 1u);
            __syncthreads();

            unsigned x = (tid < 256) ? s_hb[tid] : 0u;
            unsigned cnt = x;
            for (int off = 1; off < 256; off <<= 1) {
                unsigned add = (tid < 256 && tid >= off) ? s_hb[tid - off] : 0u;
                __syncthreads();
                if (tid < 256) { x += add; s_hb[tid] = x; }
                __syncthreads();
            }
            if (tid < 256) s_rb[tid] = x - cnt;   // exclusive base
            __syncthreads();

            for (int w = 0; w < nwv; ++w) {
                for (int j = tid; j < 32 * 256; j += NTHR) ((unsigned*)wc)[j] = 0u;
                __syncthreads();
                int e = (w << 10) + tid;
                unsigned key = sk[e];
                unsigned d = (key >> sh) & 255u;
                unsigned mask = __match_any_sync(0xffffffffu, d);
                unsigned lr = __popc(mask & ((1u << lane) - 1u));
                if (lr == 0) wc[wid][d] = __popc(mask);
                __syncthreads();
                if (tid < 256) {
                    unsigned run = s_rb[tid];
                    #pragma unroll
                    for (int ww = 0; ww < 32; ++ww) {
                        unsigned c2 = wc[ww][tid];
                        wc[ww][tid] = run;
                        run += c2;
                    }
                    s_rb[tid] = run;
                }
                __syncthreads();
                unsigned dst = wc[wid][d] + lr;
                dk[dst] = key;
                dv[dst] = sv[e];
                __syncthreads();
            }
        }
        // result in ka/va (slots)

        // ---- exact tie-break: equal keys -> ascending original box idx ----
        for (int i = tid; i < C; i += NTHR)
            if (i > 0 && ka[i] == ka[i - 1]) atomicAdd(&s_nties, 1);
        __syncthreads();
        if (s_nties) {
            for (int i = tid; i < C; i += NTHR) {
                if ((i == 0 || ka[i] != ka[i - 1]) && i + 1 < C && ka[i + 1] == ka[i]) {
                    int j = i + 1;
                    while (j < C && ka[j] == ka[i]) j++;
                    for (int a = i + 1; a < j; ++a) {
                        unsigned slot = va[a];
                        unsigned key2 = g_candV[slot];
                        int p2 = a - 1;
                        while (p2 >= i && g_candV[va[p2]] > key2) { va[p2 + 1] = va[p2]; --p2; }
                        va[p2 + 1] = slot;
                    }
                }
            }
        }
        __syncthreads();

        // ---- gather candidate boxes in sorted order ----
        for (int i = tid; i < C; i += NTHR) sBox[i] = g_candBox[va[i]];
        __syncthreads();

        // ---- block-parallel chunked greedy NMS ----
        {
            int nsel = 0;
            for (int base = 0; base < C && nsel < MAXB; base += NTHR) {
                int i = base + tid;
                float4 bx = make_float4(0.f, 0.f, 0.f, 0.f);
                float ar = 0.f;
                bool alive = (i < C);
                if (alive) {
                    bx = sBox[i];
                    ar = (bx.z - bx.x) * (bx.w - bx.y);
                    for (int s = 0; s < nsel; ++s) {
                        if (iou_gt_half(bx, ar, selB[s], selA[s])) { alive = false; break; }
                    }
                }
                unsigned bal = __ballot_sync(0xffffffffu, alive);
                if (lane == 0) s_alive[wid] = bal;
                __syncthreads();

                int hint = 0;
                while (nsel < MAXB) {
                    if (tid == 0) {
                        int f = -1;
                        for (int w2 = hint; w2 < 32; ++w2) {
                            unsigned m2 = s_alive[w2];
                            if (m2) { f = (w2 << 5) + __ffs(m2) - 1; break; }
                        }
                        s_first = f;
                        if (f >= 0) s_opos[nsel] = base + f;
                    }
                    __syncthreads();
                    int f = s_first;
                    if (f < 0) break;
                    hint = f >> 5;
                    float4 sb = sBox[base + f];
                    float sa = (sb.z - sb.x) * (sb.w - sb.y);
                    if (tid == f) { selB[nsel] = bx; selA[nsel] = ar; }
                    nsel++;
                    if (alive && (tid == f || iou_gt_half(bx, ar, sb, sa))) alive = false;
                    unsigned bal2 = __ballot_sync(0xffffffffu, alive);
                    if (lane == 0) s_alive[wid] = bal2;
                    __syncthreads();
                }
            }
            if (tid == 0) s_nsel = nsel;
        }
        __syncthreads();

        // ---- fill output arrays ----
        int ns = s_nsel;
        for (int j = tid; j < ns; j += NTHR) {
            int i = s_opos[j];
            o_box[j]   = sBox[i];
            o_score[j] = dec_ord(~ka[i]);
            o_cls[j]   = g_candCls[va[i]];
        }
        __syncthreads();
    }

    // ================= fallback (exactness guard; normally never taken) =================
    {
        bool need_fb = (s_nsel < MAXB) && (ovf || totalvalid > (unsigned)C);
        if (need_fb) {
            for (int gw = tid; gw < NTOT; gw += NTHR) {
                int H, abase, local;
                const float* p = box_ptr(gw, g0, g1, g2, H, abase, local);
                g_bboxFB[gw] = geom(p, local, H, abase, anch);
            }
            if (tid == 0) s_nsel = 0;
            __syncthreads();
            unsigned long long* red = (unsigned long long*)kb;
            for (int r = 0; r < MAXB; ++r) {
                unsigned long long best = ~0ull;
                for (int i = tid; i < NTOT; i += NTHR) {
                    unsigned k = g_keysA[i];
                    if (k < 0x80000000u) {
                        unsigned long long cmp = ((unsigned long long)k << 32) | (unsigned)i;
                        if (cmp < best) best = cmp;
                    }
                }
                red[tid] = best;
                __syncthreads();
                for (int off = 512; off; off >>= 1) {
                    if (tid < off && red[tid + off] < red[tid]) red[tid] = red[tid + off];
                    __syncthreads();
                }
                best = red[0];
                __syncthreads();
                if (best == ~0ull) break;
                unsigned j = (unsigned)(best & 0xFFFFFFFFu);
                float4 bj = g_bboxFB[j];
                float aj = (bj.z - bj.x) * (bj.w - bj.y);
                if (tid == 0) {
                    int n = s_nsel;
                    o_box[n]   = bj;
                    o_score[n] = dec_ord(~(unsigned)(best >> 32));
                    s_fbidx[n] = (int)j;
                    s_nsel = n + 1;
                }
                for (int i = tid; i < NTOT; i += NTHR) {
                    unsigned k = g_keysA[i];
                    if (k < 0x80000000u) {
                        float4 bi = g_bboxFB[i];
                        float ai = (bi.z - bi.x) * (bi.w - bi.y);
                        if (iou_gt_half(bi, ai, bj, aj)) g_keysA[i] = 0xFFFFFFFFu;
                    }
                }
                __syncthreads();
            }
            for (int j2 = tid; j2 < s_nsel; j2 += NTHR) {
                int gw = s_fbidx[j2];
                int H, abase, local;
                const float* p = box_ptr(gw, g0, g1, g2, H, abase, local);
                float bestv = -3.4e38f; int bi = 0;
                for (int c = 0; c < 80; ++c) {
                    float v = p[5 + c];
                    if (v > bestv) { bestv = v; bi = c; }
                }
                o_cls[j2] = bi;
            }
            __syncthreads();
        }
    }

    // ================= output =================
    int ns = s_nsel;
    for (int i = tid; i < out_size; i += NTHR) {
        float v = 0.0f;
        if (i < 400) {
            int j = i >> 2;
            if (j < ns) v = ((float*)o_box)[i];
        } else if (i < 500) {
            int j = i - 400;
            if (j < ns) v = o_score[j];
        } else if (i < 600) {
            int j = i - 500;
            if (j < ns) v = (float)o_cls[j];
        } else if (i == 600) {
            v = (float)ns;
        }
        out[i] = v;
    }

    // ---- self-clean persistent state for next launch (all blocks already exited) ----
    __syncthreads();
    if (tid == 0) {
        g_barcnt = 0u;
        g_barrel = 0u;
        g_done   = 0u;
    }
}

// ---------------- launch ----------------
extern "C" void kernel_launch(void* const* d_in, const int* in_sizes, int n_in,
                              void* d_out, int out_size) {
    const float* g0   = (const float*)d_in[0];
    const float* g1   = (const float*)d_in[1];
    const float* g2   = (const float*)d_in[2];
    const float* anch = (const float*)d_in[3];
    float* out = (float*)d_out;

    cudaFuncSetAttribute(k1_kernel, cudaFuncAttributeMaxDynamicSharedMemorySize, K1SM);
    cudaFuncSetAttribute(k2_kernel, cudaFuncAttributeMaxDynamicSharedMemorySize, DSBYTES);
    k1_kernel<<<NB1, K1T, K1SM>>>(g0, g1, g2);
    k2_kernel<<<NBLK, NTHR, DSBYTES>>>(g0, g1, g2, anch, out, out_size);
}